// round 9
// baseline (speedup 1.0000x reference)
#include <cuda_runtime.h>
#include <cuda_bf16.h>

#define DIM   128
#define NNB   64

// Block = 128 threads = 4 warps, processes 2 batch rows.
// Warps {0,1} split row b0's 64 neighbors (32 each); warps {2,3} split row b1.
// Doubles resident warps vs one-warp-per-row -> higher time-average
// outstanding-load count chip-wide (attacks the 37% DRAM-idle gap).
__global__ void __launch_bounds__(128, 9)
net_gather_kernel(const int* __restrict__ data_r,
                  const int* __restrict__ data_e,
                  const int* __restrict__ rel,
                  const int* __restrict__ pos_id,
                  const int* __restrict__ neg_id,
                  const float* __restrict__ ent_emb,
                  const float* __restrict__ edge_w,
                  const float* __restrict__ rel_emb,
                  float* __restrict__ out,
                  int B)
{
    const int w    = threadIdx.x >> 5;          // 0..3
    const int lane = threadIdx.x & 31;
    const int row  = w >> 1;                    // 0 or 1 within block
    const int half = w & 1;                     // which 32 neighbors
    const int b    = blockIdx.x * 2 + row;

    __shared__ int    s_e[4][32];               // each warp's 32 gather offsets
    __shared__ float4 s_part[2][32];            // partial sums from odd warps

    // Each warp stages its own 32 neighbor indices (prescaled to float4 rows).
    const int base = b * NNB;
    s_e[w][lane] = data_e[base + half * 32 + lane] * (DIM / 4);

    // Full 64-logit softmax, computed redundantly by each warp of the pair.
    float l0 = __ldg(&edge_w[data_r[base + lane]]);
    float l1 = __ldg(&edge_w[data_r[base + 32 + lane]]);
    float m = fmaxf(l0, l1);
    #pragma unroll
    for (int off = 16; off > 0; off >>= 1)
        m = fmaxf(m, __shfl_xor_sync(0xffffffffu, m, off));
    float x0 = __expf(l0 - m);
    float x1 = __expf(l1 - m);
    float s = x0 + x1;
    #pragma unroll
    for (int off = 16; off > 0; off >>= 1)
        s += __shfl_xor_sync(0xffffffffu, s, off);
    float inv = __frcp_rn(s);
    // This warp's 32 weights live one-per-lane (position half*32 + lane).
    float wlane = (half == 0 ? x0 : x1) * inv;
    __syncwarp();

    const float4* __restrict__ emb4 = (const float4*)ent_emb;   // row stride 32

    // Per-row side lookups, split across the warp pair (issued early).
    float4 rv, pv, nv;
    if (half == 0) {
        rv = __ldg(&((const float4*)rel_emb)[rel[b] * (DIM / 4) + lane]);
    } else {
        pv = __ldcg(&emb4[pos_id[b] * (DIM / 4) + lane]);
        nv = __ldcg(&emb4[neg_id[b] * (DIM / 4) + lane]);
    }

    // Gather 32 neighbors: 8 LDG.128 in flight per chunk, weights via shfl.
    float4 A = make_float4(0.f, 0.f, 0.f, 0.f);
    float4 C = make_float4(0.f, 0.f, 0.f, 0.f);
    #pragma unroll
    for (int j = 0; j < 32; j += 8) {
        float4 v[8];
        #pragma unroll
        for (int k = 0; k < 8; k++)
            v[k] = __ldcg(&emb4[s_e[w][j + k] + lane]);
        #pragma unroll
        for (int k = 0; k < 8; k += 2) {
            float wa = __shfl_sync(0xffffffffu, wlane, j + k);
            float wb = __shfl_sync(0xffffffffu, wlane, j + k + 1);
            A.x = fmaf(wa, v[k].x, A.x);  C.x = fmaf(wb, v[k + 1].x, C.x);
            A.y = fmaf(wa, v[k].y, A.y);  C.y = fmaf(wb, v[k + 1].y, C.y);
            A.z = fmaf(wa, v[k].z, A.z);  C.z = fmaf(wb, v[k + 1].z, C.z);
            A.w = fmaf(wa, v[k].w, A.w);  C.w = fmaf(wb, v[k + 1].w, C.w);
        }
    }
    A.x += C.x; A.y += C.y; A.z += C.z; A.w += C.w;

    float4* out4 = (float4*)out;
    const int bd = b * (DIM / 4) + lane;
    const int BD = B * (DIM / 4);

    if (half == 1) {
        s_part[row][lane] = A;          // hand partial to even warp
        __stcs(&out4[BD + bd],     pv); // pos/neg copies owned by odd warp
        __stcs(&out4[2 * BD + bd], nv);
    }
    __syncthreads();
    if (half == 0) {
        float4 P = s_part[row][lane];
        float4 o;
        o.x = A.x + P.x + rv.x;
        o.y = A.y + P.y + rv.y;
        o.z = A.z + P.z + rv.z;
        o.w = A.w + P.w + rv.w;
        __stcs(&out4[bd], o);
    }
}

extern "C" void kernel_launch(void* const* d_in, const int* in_sizes, int n_in,
                              void* d_out, int out_size)
{
    const int*   data_r  = (const int*)  d_in[0];
    const int*   data_e  = (const int*)  d_in[1];
    const int*   rel     = (const int*)  d_in[2];
    const int*   pos_id  = (const int*)  d_in[3];
    const int*   neg_id  = (const int*)  d_in[4];
    const float* ent_emb = (const float*)d_in[5];
    const float* edge_w  = (const float*)d_in[6];
    const float* rel_emb = (const float*)d_in[7];
    float* out = (float*)d_out;

    const int B = in_sizes[2];  // rel has B elements

    net_gather_kernel<<<B / 2, 128>>>(data_r, data_e, rel, pos_id, neg_id,
                                      ent_emb, edge_w, rel_emb, out, B);
}

// round 10
// speedup vs baseline: 1.1099x; 1.1099x over previous
#include <cuda_runtime.h>
#include <cuda_bf16.h>
#include <cstdint>

#define DIM   128
#define NNB   64
#define WARPS 2        // rows per block (fine-grained load balance)

// 256-bit gather load: 8 floats (32B) per lane. A half-warp (16 lanes x 32B)
// covers one full 512B embedding row, so one LDG.256 fetches TWO rows.
__device__ __forceinline__ void ldg256(const float* __restrict__ p, float v[8]) {
    uint32_t u0,u1,u2,u3,u4,u5,u6,u7;
    asm volatile("ld.global.nc.v8.b32 {%0,%1,%2,%3,%4,%5,%6,%7}, [%8];"
                 : "=r"(u0),"=r"(u1),"=r"(u2),"=r"(u3),
                   "=r"(u4),"=r"(u5),"=r"(u6),"=r"(u7)
                 : "l"(p));
    v[0]=__uint_as_float(u0); v[1]=__uint_as_float(u1);
    v[2]=__uint_as_float(u2); v[3]=__uint_as_float(u3);
    v[4]=__uint_as_float(u4); v[5]=__uint_as_float(u5);
    v[6]=__uint_as_float(u6); v[7]=__uint_as_float(u7);
}

__global__ void __launch_bounds__(32 * WARPS, 16)
net_gather_kernel(const int* __restrict__ data_r,
                  const int* __restrict__ data_e,
                  const int* __restrict__ rel,
                  const int* __restrict__ pos_id,
                  const int* __restrict__ neg_id,
                  const float* __restrict__ ent_emb,
                  const float* __restrict__ edge_w,
                  const float* __restrict__ rel_emb,
                  float* __restrict__ out,
                  int B)
{
    const int w    = threadIdx.x >> 5;
    const int lane = threadIdx.x & 31;
    const int b    = blockIdx.x * WARPS + w;

    const int halfsel = lane >> 4;     // row parity this lane serves
    const int sub     = lane & 15;     // 32B sub-block within the 512B row

    __shared__ int   s_e[WARPS][NNB];  // entity row index * 128 (float stride)
    __shared__ float s_w[WARPS][NNB];  // softmax weights

    // Stage indices (prescaled to float row offset) and edge logits.
    const int base = b * NNB;
    s_e[w][lane]      = data_e[base + lane]      * DIM;
    s_e[w][lane + 32] = data_e[base + lane + 32] * DIM;
    float l0 = __ldg(&edge_w[data_r[base + lane]]);
    float l1 = __ldg(&edge_w[data_r[base + lane + 32]]);

    // Warp-local softmax over 64 logits (2 per lane).
    float m = fmaxf(l0, l1);
    #pragma unroll
    for (int off = 16; off > 0; off >>= 1)
        m = fmaxf(m, __shfl_xor_sync(0xffffffffu, m, off));
    float x0 = __expf(l0 - m);
    float x1 = __expf(l1 - m);
    float s = x0 + x1;
    #pragma unroll
    for (int off = 16; off > 0; off >>= 1)
        s += __shfl_xor_sync(0xffffffffu, s, off);
    float inv = __frcp_rn(s);
    s_w[w][lane]      = x0 * inv;
    s_w[w][lane + 32] = x1 * inv;
    __syncwarp();

    const float4* __restrict__ emb4 = (const float4*)ent_emb;   // row stride 32

    // Independent per-row lookups (float4-per-lane layout), issued early.
    float4 rv = __ldg(&((const float4*)rel_emb)[rel[b] * (DIM / 4) + lane]);
    float4 pv = __ldcg(&emb4[pos_id[b] * (DIM / 4) + lane]);
    float4 nv = __ldcg(&emb4[neg_id[b] * (DIM / 4) + lane]);

    // Gather: 4 LDG.256 in flight per chunk = 8 rows (4KB) outstanding.
    // Lane accumulates dims [sub*8, sub*8+8) over rows of parity `halfsel`.
    float acc[8] = {0.f,0.f,0.f,0.f,0.f,0.f,0.f,0.f};
    const int foff = sub * 8;
    #pragma unroll
    for (int j = 0; j < NNB; j += 8) {
        float v[4][8];
        #pragma unroll
        for (int k = 0; k < 4; k++) {
            int ridx = s_e[w][j + 2 * k + halfsel];
            ldg256(&ent_emb[ridx + foff], v[k]);
        }
        #pragma unroll
        for (int k = 0; k < 4; k++) {
            float wt = s_w[w][j + 2 * k + halfsel];
            #pragma unroll
            for (int d = 0; d < 8; d++)
                acc[d] = fmaf(wt, v[k][d], acc[d]);
        }
    }

    // Combine row parities: lane l and lane l^16 hold the same dims.
    #pragma unroll
    for (int d = 0; d < 8; d++)
        acc[d] += __shfl_xor_sync(0xffffffffu, acc[d], 16);

    float4* out4 = (float4*)out;
    const int BD = B * (DIM / 4);
    const int bd = b * (DIM / 4) + lane;

    // rel_emb add + out_t store: lanes 0-15 own dims [sub*8, sub*8+8).
    // rv is in float4-per-lane layout, so fetch the two needed float4s via shfl.
    // Simpler: lanes 0-15 reload rel row in 8-float layout (L2-hot, cheap).
    if (halfsel == 0) {
        float rv8[8];
        ldg256(&rel_emb[rel[b] * DIM + foff], rv8);
        float4 o0, o1;
        o0.x = acc[0] + rv8[0]; o0.y = acc[1] + rv8[1];
        o0.z = acc[2] + rv8[2]; o0.w = acc[3] + rv8[3];
        o1.x = acc[4] + rv8[4]; o1.y = acc[5] + rv8[5];
        o1.z = acc[6] + rv8[6]; o1.w = acc[7] + rv8[7];
        __stcs(&out4[b * (DIM / 4) + 2 * sub],     o0);
        __stcs(&out4[b * (DIM / 4) + 2 * sub + 1], o1);
    }
    (void)rv;
    __stcs(&out4[BD + bd],     pv);
    __stcs(&out4[2 * BD + bd], nv);
}

extern "C" void kernel_launch(void* const* d_in, const int* in_sizes, int n_in,
                              void* d_out, int out_size)
{
    const int*   data_r  = (const int*)  d_in[0];
    const int*   data_e  = (const int*)  d_in[1];
    const int*   rel     = (const int*)  d_in[2];
    const int*   pos_id  = (const int*)  d_in[3];
    const int*   neg_id  = (const int*)  d_in[4];
    const float* ent_emb = (const float*)d_in[5];
    const float* edge_w  = (const float*)d_in[6];
    const float* rel_emb = (const float*)d_in[7];
    float* out = (float*)d_out;

    const int B = in_sizes[2];  // rel has B elements

    net_gather_kernel<<<B / WARPS, 32 * WARPS>>>(data_r, data_e, rel,
                                                 pos_id, neg_id,
                                                 ent_emb, edge_w, rel_emb,
                                                 out, B);
}

// round 11
// speedup vs baseline: 1.1271x; 1.0155x over previous
#include <cuda_runtime.h>
#include <cuda_bf16.h>
#include <cstdint>

#define DIM   128
#define NNB   64
#define WARPS 2        // rows per block (fine-grained load balance)

// 256-bit gather load: 8 floats (32B) per lane. A half-warp (16 lanes x 32B)
// covers one full 512B embedding row, so one LDG.256 fetches TWO rows.
__device__ __forceinline__ void ldg256(const float* __restrict__ p, float v[8]) {
    uint32_t u0,u1,u2,u3,u4,u5,u6,u7;
    asm volatile("ld.global.nc.v8.b32 {%0,%1,%2,%3,%4,%5,%6,%7}, [%8];"
                 : "=r"(u0),"=r"(u1),"=r"(u2),"=r"(u3),
                   "=r"(u4),"=r"(u5),"=r"(u6),"=r"(u7)
                 : "l"(p));
    v[0]=__uint_as_float(u0); v[1]=__uint_as_float(u1);
    v[2]=__uint_as_float(u2); v[3]=__uint_as_float(u3);
    v[4]=__uint_as_float(u4); v[5]=__uint_as_float(u5);
    v[6]=__uint_as_float(u6); v[7]=__uint_as_float(u7);
}

__global__ void __launch_bounds__(32 * WARPS, 16)
net_gather_kernel(const int* __restrict__ data_r,
                  const int* __restrict__ data_e,
                  const int* __restrict__ rel,
                  const int* __restrict__ pos_id,
                  const int* __restrict__ neg_id,
                  const float* __restrict__ ent_emb,
                  const float* __restrict__ edge_w,
                  const float* __restrict__ rel_emb,
                  float* __restrict__ out,
                  int B)
{
    const int w    = threadIdx.x >> 5;
    const int lane = threadIdx.x & 31;
    const int b    = blockIdx.x * WARPS + w;

    const int halfsel = lane >> 4;     // row parity this lane serves
    const int sub     = lane & 15;     // 32B sub-block within the 512B row
    const int foff    = sub * 8;

    __shared__ int   s_e[WARPS][NNB];  // entity row index * 128 (float stride)
    __shared__ float s_w[WARPS][NNB];  // softmax weights

    // Stage indices first — gather loads depend ONLY on these.
    const int base = b * NNB;
    int e0 = data_e[base + lane]      * DIM;
    int e1 = data_e[base + lane + 32] * DIM;
    s_e[w][lane]      = e0;
    s_e[w][lane + 32] = e1;
    __syncwarp();

    // Issue the FIRST gather chunk (8 rows) before computing the softmax,
    // hiding the softmax's shfl/exp latency behind the first DRAM round-trip.
    float vpre[4][8];
    #pragma unroll
    for (int k = 0; k < 4; k++)
        ldg256(&ent_emb[s_e[w][2 * k + halfsel] + foff], vpre[k]);

    // Per-row side lookups (independent), also in flight early.
    const float4* __restrict__ emb4 = (const float4*)ent_emb;   // row stride 32
    float4 pv = __ldcg(&emb4[pos_id[b] * (DIM / 4) + lane]);
    float4 nv = __ldcg(&emb4[neg_id[b] * (DIM / 4) + lane]);
    const int relrow = rel[b] * DIM;

    // Warp-local softmax over 64 logits (2 per lane) — overlaps loads above.
    float l0 = __ldg(&edge_w[data_r[base + lane]]);
    float l1 = __ldg(&edge_w[data_r[base + lane + 32]]);
    float m = fmaxf(l0, l1);
    #pragma unroll
    for (int off = 16; off > 0; off >>= 1)
        m = fmaxf(m, __shfl_xor_sync(0xffffffffu, m, off));
    float x0 = __expf(l0 - m);
    float x1 = __expf(l1 - m);
    float s = x0 + x1;
    #pragma unroll
    for (int off = 16; off > 0; off >>= 1)
        s += __shfl_xor_sync(0xffffffffu, s, off);
    float inv = __frcp_rn(s);
    s_w[w][lane]      = x0 * inv;
    s_w[w][lane + 32] = x1 * inv;
    __syncwarp();

    // Gather mainloop: consume prefetched chunk, keep 4 LDG.256 (8 rows, 4KB)
    // in flight per iteration.
    float acc[8] = {0.f,0.f,0.f,0.f,0.f,0.f,0.f,0.f};
    #pragma unroll
    for (int j = 0; j < NNB; j += 8) {
        float v[4][8];
        if (j + 8 < NNB) {
            #pragma unroll
            for (int k = 0; k < 4; k++)
                ldg256(&ent_emb[s_e[w][j + 8 + 2 * k + halfsel] + foff], v[k]);
        }
        #pragma unroll
        for (int k = 0; k < 4; k++) {
            float wt = s_w[w][j + 2 * k + halfsel];
            #pragma unroll
            for (int d = 0; d < 8; d++)
                acc[d] = fmaf(wt, vpre[k][d], acc[d]);
        }
        #pragma unroll
        for (int k = 0; k < 4; k++)
            #pragma unroll
            for (int d = 0; d < 8; d++)
                vpre[k][d] = v[k][d];
    }

    // Combine row parities: lane l and lane l^16 hold the same dims.
    #pragma unroll
    for (int d = 0; d < 8; d++)
        acc[d] += __shfl_xor_sync(0xffffffffu, acc[d], 16);

    float4* out4 = (float4*)out;
    const int BD = B * (DIM / 4);
    const int bd = b * (DIM / 4) + lane;

    // out_t: lanes 0-15 own dims [sub*8, sub*8+8); add rel row (L2-hot).
    if (halfsel == 0) {
        float rv8[8];
        ldg256(&rel_emb[relrow + foff], rv8);
        float4 o0, o1;
        o0.x = acc[0] + rv8[0]; o0.y = acc[1] + rv8[1];
        o0.z = acc[2] + rv8[2]; o0.w = acc[3] + rv8[3];
        o1.x = acc[4] + rv8[4]; o1.y = acc[5] + rv8[5];
        o1.z = acc[6] + rv8[6]; o1.w = acc[7] + rv8[7];
        __stcs(&out4[b * (DIM / 4) + 2 * sub],     o0);
        __stcs(&out4[b * (DIM / 4) + 2 * sub + 1], o1);
    }
    __stcs(&out4[BD + bd],     pv);
    __stcs(&out4[2 * BD + bd], nv);
}

extern "C" void kernel_launch(void* const* d_in, const int* in_sizes, int n_in,
                              void* d_out, int out_size)
{
    const int*   data_r  = (const int*)  d_in[0];
    const int*   data_e  = (const int*)  d_in[1];
    const int*   rel     = (const int*)  d_in[2];
    const int*   pos_id  = (const int*)  d_in[3];
    const int*   neg_id  = (const int*)  d_in[4];
    const float* ent_emb = (const float*)d_in[5];
    const float* edge_w  = (const float*)d_in[6];
    const float* rel_emb = (const float*)d_in[7];
    float* out = (float*)d_out;

    const int B = in_sizes[2];  // rel has B elements

    net_gather_kernel<<<B / WARPS, 32 * WARPS>>>(data_r, data_e, rel,
                                                 pos_id, neg_id,
                                                 ent_emb, edge_w, rel_emb,
                                                 out, B);
}